// round 13
// baseline (speedup 1.0000x reference)
#include <cuda_runtime.h>
#include <cuda_bf16.h>
#include <cstdint>

// Problem constants (fixed by the reference)
#define BB   4
#define CC   16
#define N1   100000
#define ND1  50000
#define E1   1600000
#define N2   50000      // == ND1
#define ND2  25000
#define E2   800000
#define NODE_F (BB*CC)  // 64 floats per node, node-major layout
#define NEG_SLOPE 0.01f

// -------- device scratch (static allocations; no runtime alloc) --------
// __align__(256): v4 reds and float4 loads require 16B alignment minimum.
__device__ __align__(256) float g_Xt  [(size_t)N1  * NODE_F];  // transposed X, node-major
__device__ __align__(256) float g_agg1[(size_t)ND1 * NODE_F];
__device__ __align__(256) float g_deg1[ND1];
__device__ __align__(256) float g_h1  [(size_t)ND1 * NODE_F];  // layer-1 out, node-major
__device__ __align__(256) float g_agg2[(size_t)ND2 * NODE_F];
__device__ __align__(256) float g_deg2[ND2];

// -------- helpers --------
__device__ __forceinline__ void red_add_v4(float* p, float a, float b, float c, float d) {
    asm volatile("red.global.add.v4.f32 [%0], {%1,%2,%3,%4};"
                 :: "l"(p), "f"(a), "f"(b), "f"(c), "f"(d) : "memory");
}
__device__ __forceinline__ void red_add_f32(float* p, float a) {
    asm volatile("red.global.add.f32 [%0], %1;" :: "l"(p), "f"(a) : "memory");
}

// -------- kernel 1: transpose X [B, N, C] -> Xt [N, B*C] (float4 granularity) --------
__global__ void k_transpose(const float4* __restrict__ X4, float4* __restrict__ Xt4) {
    int t = blockIdx.x * blockDim.x + threadIdx.x;       // [0, N1*16)
    if (t >= N1 * 16) return;
    int n  = t >> 4;
    int q  = t & 15;          // q = b*4 + c4
    int b  = q >> 2;
    int c4 = q & 3;
    // X4 layout: [(b*N1 + n)*4 + c4]
    Xt4[t] = X4[((size_t)b * N1 + n) * 4 + c4];
}

// -------- kernel 2: edge scatter (16 lanes per edge) + degree on lane 0 --------
// Edge metadata loaded once per 16-lane half-warp, broadcast via shfl.
// NOTE: launch counts are exact multiples of blockDim (verified for all call
// sites), so every warp is full and the full-mask shfl is safe.
__global__ void k_scatter(const float4* __restrict__ Xt4,
                          const int* __restrict__ src,
                          const int* __restrict__ dst,
                          const float* __restrict__ ew,
                          float* __restrict__ agg,
                          float* __restrict__ deg,
                          int E) {
    long long g = (long long)blockIdx.x * blockDim.x + threadIdx.x;
    if (g >= (long long)E * 16) return;
    int e = (int)(g >> 4);
    int lane = threadIdx.x & 31;
    int l = lane & 15;                 // slot within edge group
    int leader = lane & 16;            // lane 0 or 16 within warp

    int s = 0, d = 0; float w = 0.0f;
    if (l == 0) {
        s = __ldg(&src[e]);
        d = __ldg(&dst[e]);
        w = __ldg(&ew[e]);
    }
    s = __shfl_sync(0xffffffffu, s, leader);
    d = __shfl_sync(0xffffffffu, d, leader);
    w = __shfl_sync(0xffffffffu, w, leader);

    float4 v = Xt4[(size_t)s * 16 + l];
    float* p = agg + (size_t)d * NODE_F + l * 4;
    red_add_v4(p, w * v.x, w * v.y, w * v.z, w * v.w);
    if (l == 0) red_add_f32(&deg[d], 1.0f);
}

// -------- kernel 3: combine: concat(X[res], agg/deg) @ W + bias, leaky-relu --------
// OUT_NODE_MAJOR=1 -> write out[n*64 + b*16 + j]  (feeds next layer)
// OUT_NODE_MAJOR=0 -> write out[b*ND*16 + n*16 + j] (final [B, ND, 16] output)
template <int OUT_NODE_MAJOR>
__global__ void k_combine(const float* __restrict__ Xt,      // source features, node-major
                          const float* __restrict__ agg,
                          const float* __restrict__ deg,
                          const int* __restrict__ res_n_id,
                          const float* __restrict__ W,       // [32, 16] row-major
                          const float* __restrict__ bias,    // [16]
                          float* __restrict__ out,
                          int ND) {
    __shared__ float Ws[32 * 16];
    __shared__ float bs[16];
    int tid = threadIdx.x;
    for (int i = tid; i < 32 * 16; i += blockDim.x) Ws[i] = W[i];
    if (tid < 16) bs[tid] = bias[tid];
    __syncthreads();

    int idx = blockIdx.x * blockDim.x + tid;               // [0, ND*B)
    if (idx >= ND * BB) return;
    int n = idx >> 2;           // node
    int b = idx & 3;            // batch

    int rn = __ldg(&res_n_id[n]);
    const float4* xr4 = (const float4*)(Xt + (size_t)rn * NODE_F + b * CC);
    const float4* ag4 = (const float4*)(agg + (size_t)n * NODE_F + b * CC);
    float invd = 1.0f / fmaxf(__ldg(&deg[n]), 1.0f);

    float h[32];
    #pragma unroll
    for (int q = 0; q < 4; q++) {
        float4 x = xr4[q];
        h[q*4+0] = x.x; h[q*4+1] = x.y; h[q*4+2] = x.z; h[q*4+3] = x.w;
        float4 a = ag4[q];
        h[16+q*4+0] = a.x * invd; h[16+q*4+1] = a.y * invd;
        h[16+q*4+2] = a.z * invd; h[16+q*4+3] = a.w * invd;
    }

    float o[16];
    #pragma unroll
    for (int j = 0; j < 16; j++) o[j] = bs[j];
    #pragma unroll
    for (int c = 0; c < 32; c++) {
        float hv = h[c];
        #pragma unroll
        for (int j = 0; j < 16; j++) o[j] = fmaf(hv, Ws[c * 16 + j], o[j]);
    }
    #pragma unroll
    for (int j = 0; j < 16; j++) {
        float v = o[j];
        o[j] = (v > 0.0f) ? v : NEG_SLOPE * v;
    }

    float4* po;
    if (OUT_NODE_MAJOR)
        po = (float4*)(out + (size_t)n * NODE_F + b * CC);
    else
        po = (float4*)(out + ((size_t)b * ND + n) * CC);
    #pragma unroll
    for (int q = 0; q < 4; q++)
        po[q] = make_float4(o[q*4+0], o[q*4+1], o[q*4+2], o[q*4+3]);
}

// -------- launch --------
extern "C" void kernel_launch(void* const* d_in, const int* in_sizes, int n_in,
                              void* d_out, int out_size) {
    const float* X    = (const float*)d_in[0];
    const float* W1   = (const float*)d_in[1];
    const float* b1   = (const float*)d_in[2];
    const float* W2   = (const float*)d_in[3];
    const float* b2   = (const float*)d_in[4];
    const float* ew1  = (const float*)d_in[5];
    const float* ew2  = (const float*)d_in[6];
    const int* src1   = (const int*)d_in[7];
    const int* dst1   = (const int*)d_in[8];
    const int* src2   = (const int*)d_in[9];
    const int* dst2   = (const int*)d_in[10];
    const int* res1   = (const int*)d_in[11];
    const int* res2   = (const int*)d_in[12];
    float* out        = (float*)d_out;

    void *p_Xt, *p_agg1, *p_deg1, *p_h1, *p_agg2, *p_deg2;
    cudaGetSymbolAddress(&p_Xt,   g_Xt);
    cudaGetSymbolAddress(&p_agg1, g_agg1);
    cudaGetSymbolAddress(&p_deg1, g_deg1);
    cudaGetSymbolAddress(&p_h1,   g_h1);
    cudaGetSymbolAddress(&p_agg2, g_agg2);
    cudaGetSymbolAddress(&p_deg2, g_deg2);

    // zero accumulators (graph-capturable async memsets)
    cudaMemsetAsync(p_agg1, 0, sizeof(float) * (size_t)ND1 * NODE_F, 0);
    cudaMemsetAsync(p_deg1, 0, sizeof(float) * ND1, 0);
    cudaMemsetAsync(p_agg2, 0, sizeof(float) * (size_t)ND2 * NODE_F, 0);
    cudaMemsetAsync(p_deg2, 0, sizeof(float) * ND2, 0);

    const int TB = 256;
    const int TS = 512;   // scatter blocks: more resident loads per SM for MLP

    // 1. transpose X -> Xt (node-major)
    {
        int nthr = N1 * 16;
        k_transpose<<<(nthr + TB - 1) / TB, TB>>>((const float4*)X, (float4*)p_Xt);
    }
    // 2. layer-1 scatter
    {
        long long nthr = (long long)E1 * 16;
        k_scatter<<<(unsigned)((nthr + TS - 1) / TS), TS>>>(
            (const float4*)p_Xt, src1, dst1, ew1,
            (float*)p_agg1, (float*)p_deg1, E1);
    }
    // 3. layer-1 combine -> h1 (node-major)
    {
        int nthr = ND1 * BB;
        k_combine<1><<<(nthr + TB - 1) / TB, TB>>>(
            (const float*)p_Xt, (const float*)p_agg1, (const float*)p_deg1,
            res1, W1, b1, (float*)p_h1, ND1);
    }
    // 4. layer-2 scatter (source features = h1)
    {
        long long nthr = (long long)E2 * 16;
        k_scatter<<<(unsigned)((nthr + TS - 1) / TS), TS>>>(
            (const float4*)p_h1, src2, dst2, ew2,
            (float*)p_agg2, (float*)p_deg2, E2);
    }
    // 5. layer-2 combine -> final output [B, ND2, 16]
    {
        int nthr = ND2 * BB;
        k_combine<0><<<(nthr + TB - 1) / TB, TB>>>(
            (const float*)p_h1, (const float*)p_agg2, (const float*)p_deg2,
            res2, W2, b2, out, ND2);
    }
    (void)in_sizes; (void)n_in; (void)out_size;
}

// round 15
// speedup vs baseline: 1.3112x; 1.3112x over previous
#include <cuda_runtime.h>
#include <cuda_bf16.h>
#include <cstdint>

// Problem constants (fixed by the reference)
#define BB   4
#define CC   16
#define N1   100000
#define ND1  50000
#define E1   1600000
#define N2   50000      // == ND1
#define ND2  25000
#define E2   800000
#define NODE_F (BB*CC)  // 64 floats per node, node-major layout
#define NEG_SLOPE 0.01f

#define SCAN_BS 512

// -------- device scratch (static allocations; no runtime alloc) --------
__device__ __align__(256) float  g_Xt  [(size_t)N1  * NODE_F];  // transposed X, node-major
__device__ __align__(256) float  g_agg1[(size_t)ND1 * NODE_F];  // mean-aggregated, layer 1
__device__ __align__(256) float  g_h1  [(size_t)ND1 * NODE_F];  // layer-1 out, node-major
__device__ __align__(256) float  g_agg2[(size_t)ND2 * NODE_F];
// CSR build state, layer 1
__device__ __align__(256) int    g_cnt1[ND1];        // degree -> (in-place) exclusive offsets
__device__ __align__(256) int    g_cur1[ND1];        // bucket-write cursors
__device__ __align__(256) int    g_bs1 [128];        // block sums for scan (need ceil(50000/512)=98)
__device__ __align__(256) float2 g_slot1[E1];        // (src_as_float, w) per CSR slot
// CSR build state, layer 2
__device__ __align__(256) int    g_cnt2[ND2];
__device__ __align__(256) int    g_cur2[ND2];
__device__ __align__(256) int    g_bs2 [64];         // need ceil(25000/512)=49
__device__ __align__(256) float2 g_slot2[E2];

// -------- kernel: transpose X [B, N, C] -> Xt [N, B*C] (float4 granularity) --------
__global__ void k_transpose(const float4* __restrict__ X4, float4* __restrict__ Xt4) {
    int t = blockIdx.x * blockDim.x + threadIdx.x;       // [0, N1*16)
    if (t >= N1 * 16) return;
    int n  = t >> 4;
    int q  = t & 15;          // q = b*4 + c4
    int b  = q >> 2;
    int c4 = q & 3;
    Xt4[t] = X4[((size_t)b * N1 + n) * 4 + c4];
}

// -------- kernel: per-dst degree histogram --------
__global__ void k_hist(const int* __restrict__ dst, int* __restrict__ cnt, int E) {
    int e = blockIdx.x * blockDim.x + threadIdx.x;
    if (e >= E) return;
    atomicAdd(&cnt[dst[e]], 1);
}

// -------- kernel: block-local exclusive scan (in place) + block sums --------
__global__ void k_scan_local(int* __restrict__ cnt, int* __restrict__ bsums, int ND) {
    __shared__ int sm[SCAN_BS];
    int i = blockIdx.x * SCAN_BS + threadIdx.x;
    int x = (i < ND) ? cnt[i] : 0;
    sm[threadIdx.x] = x;
    __syncthreads();
    #pragma unroll
    for (int o = 1; o < SCAN_BS; o <<= 1) {
        int t = (threadIdx.x >= o) ? sm[threadIdx.x - o] : 0;
        __syncthreads();
        sm[threadIdx.x] += t;
        __syncthreads();
    }
    if (i < ND) cnt[i] = sm[threadIdx.x] - x;     // exclusive within block
    if (threadIdx.x == SCAN_BS - 1) bsums[blockIdx.x] = sm[SCAN_BS - 1];
}

// -------- kernel: add block prefix; copy offsets into cursors --------
__global__ void k_scan_add(int* __restrict__ off, const int* __restrict__ bsums,
                           int* __restrict__ cur, int ND) {
    int b = blockIdx.x;
    int prefix = 0;
    for (int j = 0; j < b; j++) prefix += bsums[j];   // <=98 L2-cached broadcast reads
    int i = b * SCAN_BS + threadIdx.x;
    if (i < ND) {
        int v = off[i] + prefix;
        off[i] = v;
        cur[i] = v;
    }
}

// -------- kernel: bucket-write (src, w) pairs into CSR slots --------
__global__ void k_bucket(const int* __restrict__ src, const int* __restrict__ dst,
                         const float* __restrict__ ew,
                         int* __restrict__ cur, float2* __restrict__ slot, int E) {
    int e = blockIdx.x * blockDim.x + threadIdx.x;
    if (e >= E) return;
    int d = dst[e];
    int p = atomicAdd(&cur[d], 1);
    slot[p] = make_float2(__int_as_float(src[e]), ew[e]);
}

// -------- kernel: per-dst gather + mean (16 lanes per dst; no atomics) --------
__global__ void k_gather(const float4* __restrict__ Xt4,
                         const float2* __restrict__ slot,
                         const int* __restrict__ off,
                         float4* __restrict__ agg4,
                         int ND, int E) {
    int g = blockIdx.x * blockDim.x + threadIdx.x;
    if (g >= ND * 16) return;
    int d = g >> 4;
    int l = g & 15;

    int beg = __ldg(&off[d]);
    int end = (d == ND - 1) ? E : __ldg(&off[d + 1]);

    float4 acc = make_float4(0.f, 0.f, 0.f, 0.f);
    for (int j = beg; j < end; j++) {
        float2 sw = __ldg(&slot[j]);          // broadcast across the 16 lanes
        int s = __float_as_int(sw.x);
        float4 v = __ldg(&Xt4[(size_t)s * 16 + l]);
        acc.x = fmaf(sw.y, v.x, acc.x);
        acc.y = fmaf(sw.y, v.y, acc.y);
        acc.z = fmaf(sw.y, v.z, acc.z);
        acc.w = fmaf(sw.y, v.w, acc.w);
    }
    float inv = 1.0f / fmaxf((float)(end - beg), 1.0f);
    agg4[(size_t)d * 16 + l] = make_float4(acc.x * inv, acc.y * inv, acc.z * inv, acc.w * inv);
}

// -------- kernel: combine: concat(X[res], agg_mean) @ W + bias, leaky-relu --------
// OUT_NODE_MAJOR=1 -> out[n*64 + b*16 + j]; 0 -> out[b*ND*16 + n*16 + j]
template <int OUT_NODE_MAJOR>
__global__ void k_combine(const float* __restrict__ Xt,
                          const float* __restrict__ agg,   // already mean-divided
                          const int* __restrict__ res_n_id,
                          const float* __restrict__ W,     // [32, 16] row-major
                          const float* __restrict__ bias,  // [16]
                          float* __restrict__ out,
                          int ND) {
    __shared__ float Ws[32 * 16];
    __shared__ float bs[16];
    int tid = threadIdx.x;
    for (int i = tid; i < 32 * 16; i += blockDim.x) Ws[i] = W[i];
    if (tid < 16) bs[tid] = bias[tid];
    __syncthreads();

    int idx = blockIdx.x * blockDim.x + tid;               // [0, ND*B)
    if (idx >= ND * BB) return;
    int n = idx >> 2;
    int b = idx & 3;

    int rn = __ldg(&res_n_id[n]);
    const float4* xr4 = (const float4*)(Xt + (size_t)rn * NODE_F + b * CC);
    const float4* ag4 = (const float4*)(agg + (size_t)n * NODE_F + b * CC);

    float h[32];
    #pragma unroll
    for (int q = 0; q < 4; q++) {
        float4 x = xr4[q];
        h[q*4+0] = x.x; h[q*4+1] = x.y; h[q*4+2] = x.z; h[q*4+3] = x.w;
        float4 a = ag4[q];
        h[16+q*4+0] = a.x; h[16+q*4+1] = a.y; h[16+q*4+2] = a.z; h[16+q*4+3] = a.w;
    }

    float o[16];
    #pragma unroll
    for (int j = 0; j < 16; j++) o[j] = bs[j];
    #pragma unroll
    for (int c = 0; c < 32; c++) {
        float hv = h[c];
        #pragma unroll
        for (int j = 0; j < 16; j++) o[j] = fmaf(hv, Ws[c * 16 + j], o[j]);
    }
    #pragma unroll
    for (int j = 0; j < 16; j++) {
        float v = o[j];
        o[j] = (v > 0.0f) ? v : NEG_SLOPE * v;
    }

    float4* po;
    if (OUT_NODE_MAJOR)
        po = (float4*)(out + (size_t)n * NODE_F + b * CC);
    else
        po = (float4*)(out + ((size_t)b * ND + n) * CC);
    #pragma unroll
    for (int q = 0; q < 4; q++)
        po[q] = make_float4(o[q*4+0], o[q*4+1], o[q*4+2], o[q*4+3]);
}

// -------- launch --------
extern "C" void kernel_launch(void* const* d_in, const int* in_sizes, int n_in,
                              void* d_out, int out_size) {
    const float* X    = (const float*)d_in[0];
    const float* W1   = (const float*)d_in[1];
    const float* b1   = (const float*)d_in[2];
    const float* W2   = (const float*)d_in[3];
    const float* b2   = (const float*)d_in[4];
    const float* ew1  = (const float*)d_in[5];
    const float* ew2  = (const float*)d_in[6];
    const int* src1   = (const int*)d_in[7];
    const int* dst1   = (const int*)d_in[8];
    const int* src2   = (const int*)d_in[9];
    const int* dst2   = (const int*)d_in[10];
    const int* res1   = (const int*)d_in[11];
    const int* res2   = (const int*)d_in[12];
    float* out        = (float*)d_out;

    void *p_Xt, *p_agg1, *p_h1, *p_agg2;
    void *p_cnt1, *p_cur1, *p_bs1, *p_slot1;
    void *p_cnt2, *p_cur2, *p_bs2, *p_slot2;
    cudaGetSymbolAddress(&p_Xt,    g_Xt);
    cudaGetSymbolAddress(&p_agg1,  g_agg1);
    cudaGetSymbolAddress(&p_h1,    g_h1);
    cudaGetSymbolAddress(&p_agg2,  g_agg2);
    cudaGetSymbolAddress(&p_cnt1,  g_cnt1);
    cudaGetSymbolAddress(&p_cur1,  g_cur1);
    cudaGetSymbolAddress(&p_bs1,   g_bs1);
    cudaGetSymbolAddress(&p_slot1, g_slot1);
    cudaGetSymbolAddress(&p_cnt2,  g_cnt2);
    cudaGetSymbolAddress(&p_cur2,  g_cur2);
    cudaGetSymbolAddress(&p_bs2,   g_bs2);
    cudaGetSymbolAddress(&p_slot2, g_slot2);

    const int TB = 256;
    const int TS = 512;

    // zero degree counters only (agg buffers are fully written by k_gather)
    cudaMemsetAsync(p_cnt1, 0, sizeof(int) * ND1, 0);
    cudaMemsetAsync(p_cnt2, 0, sizeof(int) * ND2, 0);

    // transpose X -> Xt (node-major)
    k_transpose<<<(N1 * 16 + TB - 1) / TB, TB>>>((const float4*)X, (float4*)p_Xt);

    // ---- CSR build, layer 1 ----
    k_hist<<<(E1 + TS - 1) / TS, TS>>>(dst1, (int*)p_cnt1, E1);
    {
        int nb = (ND1 + SCAN_BS - 1) / SCAN_BS;
        k_scan_local<<<nb, SCAN_BS>>>((int*)p_cnt1, (int*)p_bs1, ND1);
        k_scan_add<<<nb, SCAN_BS>>>((int*)p_cnt1, (const int*)p_bs1, (int*)p_cur1, ND1);
    }
    k_bucket<<<(E1 + TS - 1) / TS, TS>>>(src1, dst1, ew1,
                                         (int*)p_cur1, (float2*)p_slot1, E1);
    // ---- CSR build, layer 2 ----
    k_hist<<<(E2 + TS - 1) / TS, TS>>>(dst2, (int*)p_cnt2, E2);
    {
        int nb = (ND2 + SCAN_BS - 1) / SCAN_BS;
        k_scan_local<<<nb, SCAN_BS>>>((int*)p_cnt2, (int*)p_bs2, ND2);
        k_scan_add<<<nb, SCAN_BS>>>((int*)p_cnt2, (const int*)p_bs2, (int*)p_cur2, ND2);
    }
    k_bucket<<<(E2 + TS - 1) / TS, TS>>>(src2, dst2, ew2,
                                         (int*)p_cur2, (float2*)p_slot2, E2);

    // ---- layer 1: gather + combine ----
    k_gather<<<(ND1 * 16 + TS - 1) / TS, TS>>>(
        (const float4*)p_Xt, (const float2*)p_slot1, (const int*)p_cnt1,
        (float4*)p_agg1, ND1, E1);
    k_combine<1><<<(ND1 * BB + TB - 1) / TB, TB>>>(
        (const float*)p_Xt, (const float*)p_agg1, res1, W1, b1, (float*)p_h1, ND1);

    // ---- layer 2: gather + combine ----
    k_gather<<<(ND2 * 16 + TS - 1) / TS, TS>>>(
        (const float4*)p_h1, (const float2*)p_slot2, (const int*)p_cnt2,
        (float4*)p_agg2, ND2, E2);
    k_combine<0><<<(ND2 * BB + TB - 1) / TB, TB>>>(
        (const float*)p_h1, (const float*)p_agg2, res2, W2, b2, out, ND2);

    (void)in_sizes; (void)n_in; (void)out_size;
}